// round 11
// baseline (speedup 1.0000x reference)
#include <cuda_runtime.h>
#include <cuda_fp16.h>
#include <stdint.h>

#define N_NODES 100000
#define CHANNELS 64
#define N_EDGES 4000000
#define CAP 128   // per-node in-edge capacity; P(Poisson(40) >= 128) ~ 3e-27

// Per-node in-edge buckets (rebuilt every call; graph-capturable, no allocs)
__device__ int g_cnt[N_NODES];
__device__ int g_slots[(size_t)N_NODES * CAP];
// fp16 mirror of x
__device__ __align__(16) __half g_xh[(size_t)N_NODES * CHANNELS];
// fp32 aggregated+scaled rows: norm[n] * (x[n] + sum x[src])
__device__ __align__(16) float g_agg[(size_t)N_NODES * CHANNELS];

// ---------------------------------------------------------------------------
// Kernel 1: zero counters + convert x (f32) -> g_xh (f16), fused.
// ---------------------------------------------------------------------------
__global__ void prep_kernel(const float* __restrict__ x) {
    int i = blockIdx.x * blockDim.x + threadIdx.x;
    int stride = gridDim.x * blockDim.x;
    for (int k = i; k < N_NODES; k += stride) g_cnt[k] = 0;

    const int n4 = N_NODES * CHANNELS / 4;
    const float4* x4 = (const float4*)x;
    uint2* h4 = (uint2*)g_xh;
    for (int k = i; k < n4; k += stride) {
        float4 v = x4[k];
        __half2 a = __floats2half2_rn(v.x, v.y);
        __half2 b = __floats2half2_rn(v.z, v.w);
        uint2 o;
        o.x = *(const unsigned*)&a;
        o.y = *(const unsigned*)&b;
        h4[k] = o;
    }
}

// ---------------------------------------------------------------------------
// Kernel 2: bucket edges by target. One scalar int atomic per edge.
// ---------------------------------------------------------------------------
__global__ void fill_kernel(const int* __restrict__ srcs,
                            const int* __restrict__ tgts) {
    int i = blockIdx.x * blockDim.x + threadIdx.x;
    int stride = gridDim.x * blockDim.x;
    for (int e = i; e < N_EDGES; e += stride) {
        int t = tgts[e];
        int s = srcs[e];
        int pos = atomicAdd(&g_cnt[t], 1);
        if (pos < CAP) g_slots[(size_t)t * CAP + pos] = s;
    }
}

// ---------------------------------------------------------------------------
// Kernel 3: GATHER ONLY (unchanged from R10; measured ~76us).
// ---------------------------------------------------------------------------
__global__ void __launch_bounds__(256) gather_kernel(
    const float* __restrict__ x,
    const float* __restrict__ norm) {
    const int wid = threadIdx.x >> 5;
    const int lane = threadIdx.x & 31;
    const int q = lane >> 3;        // quarter 0..3
    const int ql = lane & 7;        // lane within quarter
    const int nA = blockIdx.x * 16 + 2 * wid;      // exact: 6250*16 = 100000
    const int nB = nA + 1;
    const int myNode = (q < 2) ? nA : nB;

    const int cntA = min(g_cnt[nA], CAP);
    const int cntB = min(g_cnt[nB], CAP);
    const int myCnt = (q < 2) ? cntA : cntB;
    const int cntMax = max(cntA, cntB);

    const int slotCnt = (lane < 16) ? cntA : cntB;
    const int* __restrict__ mySlots =
        g_slots + (size_t)((lane < 16) ? nA : nB) * CAP;
    const int slotClampHi = max(slotCnt - 1, 0);
    const __half* __restrict__ xh = g_xh;

    float4 a0, a1;
    if ((q & 1) == 0) {
        const float4* xs = (const float4*)(x + (size_t)myNode * CHANNELS + ql * 8);
        a0 = xs[0];
        a1 = xs[1];
    } else {
        a0 = make_float4(0.f, 0.f, 0.f, 0.f);
        a1 = make_float4(0.f, 0.f, 0.f, 0.f);
    }

    int sidx_cur = mySlots[min(lane & 15, slotClampHi)];
    for (int e = 0; e < cntMax; e += 16) {
        int sidx_nxt = 0;
        if (e + 16 < cntMax)
            sidx_nxt = mySlots[min(e + 16 + (lane & 15), slotClampHi)];

#pragma unroll
        for (int r = 0; r < 8; r++) {
            int edgeIdx = e + 2 * r + (q & 1);
            int srcLane = ((q >= 2) ? 16 : 0) + 2 * r + (q & 1);
            int s = __shfl_sync(0xffffffffu, sidx_cur, srcLane);
            if (edgeIdx < myCnt) {
                uint4 hv = *(const uint4*)(xh + (size_t)s * CHANNELS + ql * 8);
                float2 f0 = __half22float2(*(const __half2*)&hv.x);
                float2 f1 = __half22float2(*(const __half2*)&hv.y);
                float2 f2 = __half22float2(*(const __half2*)&hv.z);
                float2 f3 = __half22float2(*(const __half2*)&hv.w);
                a0.x += f0.x; a0.y += f0.y; a0.z += f1.x; a0.w += f1.y;
                a1.x += f2.x; a1.y += f2.y; a1.z += f3.x; a1.w += f3.y;
            }
        }
        sidx_cur = sidx_nxt;
    }

    a0.x += __shfl_xor_sync(0xffffffffu, a0.x, 8);
    a0.y += __shfl_xor_sync(0xffffffffu, a0.y, 8);
    a0.z += __shfl_xor_sync(0xffffffffu, a0.z, 8);
    a0.w += __shfl_xor_sync(0xffffffffu, a0.w, 8);
    a1.x += __shfl_xor_sync(0xffffffffu, a1.x, 8);
    a1.y += __shfl_xor_sync(0xffffffffu, a1.y, 8);
    a1.z += __shfl_xor_sync(0xffffffffu, a1.z, 8);
    a1.w += __shfl_xor_sync(0xffffffffu, a1.w, 8);

    if ((q & 1) == 0) {
        float nm = norm[myNode];
        float4* dst = (float4*)(g_agg + (size_t)myNode * CHANNELS + ql * 8);
        dst[0] = make_float4(a0.x * nm, a0.y * nm, a0.z * nm, a0.w * nm);
        dst[1] = make_float4(a1.x * nm, a1.y * nm, a1.z * nm, a1.w * nm);
    }
}

// ---------------------------------------------------------------------------
// Kernel 4: out = g_agg @ W via tensor cores (mma.sync tf32).
// Warp handles 16 nodes x 64 outputs: 8 k-chunks x 8 n-tiles of m16n8k8.
// W staged in shared as tf32 with row stride 72 -> B-fragment LDS pattern
// (8*tid + gid) is exactly conflict-free. 320 threads = 10 warps/block,
// grid 625 -> 6250 warp-tasks == 100000/16 exactly.
// ---------------------------------------------------------------------------
#define WSTRIDE 72

__device__ __forceinline__ uint32_t f32_to_tf32(float f) {
    uint32_t r;
    asm("cvt.rna.tf32.f32 %0, %1;" : "=r"(r) : "f"(f));
    return r;
}

__global__ void __launch_bounds__(320) gemm_kernel(
    const float* __restrict__ W,
    float* __restrict__ out) {
    __shared__ uint32_t sW[CHANNELS * WSTRIDE];  // tf32 bits, stride 72

    for (int i = threadIdx.x; i < CHANNELS * CHANNELS; i += blockDim.x) {
        int k = i >> 6;
        int n = i & 63;
        sW[k * WSTRIDE + n] = f32_to_tf32(W[i]);
    }
    __syncthreads();

    const int wid = threadIdx.x >> 5;
    const int lane = threadIdx.x & 31;
    const int gid = lane >> 2;   // group id 0..7
    const int tid = lane & 3;    // thread in group 0..3
    const int base = (blockIdx.x * 10 + wid) * 16;  // first of 16 nodes

    const float* __restrict__ agg = g_agg;
    const size_t r0 = (size_t)(base + gid) * CHANNELS;
    const size_t r1 = (size_t)(base + gid + 8) * CHANNELS;

    float c[8][4];
#pragma unroll
    for (int nt = 0; nt < 8; nt++)
#pragma unroll
        for (int j = 0; j < 4; j++) c[nt][j] = 0.f;

#pragma unroll
    for (int kc = 0; kc < 8; kc++) {
        const int k0 = kc * 8 + tid;
        // A fragment (m16k8, row-major): a0(row gid,col tid) a1(row gid+8,col tid)
        //                                a2(col tid+4)       a3(row gid+8,col tid+4)
        uint32_t a0 = f32_to_tf32(agg[r0 + k0]);
        uint32_t a1 = f32_to_tf32(agg[r1 + k0]);
        uint32_t a2 = f32_to_tf32(agg[r0 + k0 + 4]);
        uint32_t a3 = f32_to_tf32(agg[r1 + k0 + 4]);

#pragma unroll
        for (int nt = 0; nt < 8; nt++) {
            // B fragment (k8n8, col-major): b0(k tid, n gid), b1(k tid+4, n gid)
            uint32_t b0 = sW[(kc * 8 + tid) * WSTRIDE + nt * 8 + gid];
            uint32_t b1 = sW[(kc * 8 + tid + 4) * WSTRIDE + nt * 8 + gid];
            asm volatile(
                "mma.sync.aligned.m16n8k8.row.col.f32.tf32.tf32.f32 "
                "{%0,%1,%2,%3}, {%4,%5,%6,%7}, {%8,%9}, {%0,%1,%2,%3};"
                : "+f"(c[nt][0]), "+f"(c[nt][1]), "+f"(c[nt][2]), "+f"(c[nt][3])
                : "r"(a0), "r"(a1), "r"(a2), "r"(a3), "r"(b0), "r"(b1));
        }
    }

    // C fragment (m16n8): c0(row gid, col 2tid) c1(col 2tid+1)
    //                     c2(row gid+8, col 2tid) c3(col 2tid+1)
#pragma unroll
    for (int nt = 0; nt < 8; nt++) {
        float* o0 = out + (size_t)(base + gid) * CHANNELS + nt * 8 + 2 * tid;
        float* o1 = out + (size_t)(base + gid + 8) * CHANNELS + nt * 8 + 2 * tid;
        *(float2*)o0 = make_float2(c[nt][0], c[nt][1]);
        *(float2*)o1 = make_float2(c[nt][2], c[nt][3]);
    }
}

// ---------------------------------------------------------------------------
extern "C" void kernel_launch(void* const* d_in, const int* in_sizes, int n_in,
                              void* d_out, int out_size) {
    const float* x = (const float*)d_in[0];
    const int* sources = (const int*)d_in[1];
    const int* targets = (const int*)d_in[2];
    const float* norm = (const float*)d_in[3];
    const float* weight = (const float*)d_in[4];
    float* out = (float*)d_out;

    prep_kernel<<<2048, 256>>>(x);
    fill_kernel<<<2048, 256>>>(sources, targets);

    gather_kernel<<<N_NODES / 16, 256>>>(x, norm);   // 6250 blocks
    gemm_kernel<<<625, 320>>>(weight, out);          // 6250 warp-tasks
}

// round 12
// speedup vs baseline: 1.3251x; 1.3251x over previous
#include <cuda_runtime.h>
#include <cuda_fp16.h>
#include <stdint.h>

#define N_NODES 100000
#define CHANNELS 64
#define N_EDGES 4000000
#define CAP 128   // per-node in-edge capacity; P(Poisson(40) >= 128) ~ 3e-27

// Per-node in-edge buckets (rebuilt every call; graph-capturable, no allocs)
__device__ int g_cnt[N_NODES];
__device__ int g_slots[(size_t)N_NODES * CAP];
// fp16 mirror of x
__device__ __align__(16) __half g_xh[(size_t)N_NODES * CHANNELS];
// fp32 aggregated+scaled rows: norm[n] * (x[n] + sum x[src])
__device__ __align__(16) float g_agg[(size_t)N_NODES * CHANNELS];

// ---------------------------------------------------------------------------
// Kernel 1: zero counters + convert x (f32) -> g_xh (f16), fused.
// ---------------------------------------------------------------------------
__global__ void prep_kernel(const float* __restrict__ x) {
    int i = blockIdx.x * blockDim.x + threadIdx.x;
    int stride = gridDim.x * blockDim.x;
    for (int k = i; k < N_NODES; k += stride) g_cnt[k] = 0;

    const int n4 = N_NODES * CHANNELS / 4;
    const float4* x4 = (const float4*)x;
    uint2* h4 = (uint2*)g_xh;
    for (int k = i; k < n4; k += stride) {
        float4 v = x4[k];
        __half2 a = __floats2half2_rn(v.x, v.y);
        __half2 b = __floats2half2_rn(v.z, v.w);
        uint2 o;
        o.x = *(const unsigned*)&a;
        o.y = *(const unsigned*)&b;
        h4[k] = o;
    }
}

// ---------------------------------------------------------------------------
// Kernel 2: bucket edges by target. One scalar int atomic per edge.
// ---------------------------------------------------------------------------
__global__ void fill_kernel(const int* __restrict__ srcs,
                            const int* __restrict__ tgts) {
    int i = blockIdx.x * blockDim.x + threadIdx.x;
    int stride = gridDim.x * blockDim.x;
    for (int e = i; e < N_EDGES; e += stride) {
        int t = tgts[e];
        int s = srcs[e];
        int pos = atomicAdd(&g_cnt[t], 1);
        if (pos < CAP) g_slots[(size_t)t * CAP + pos] = s;
    }
}

// ---------------------------------------------------------------------------
// Kernel 3: GATHER ONLY (unchanged; proven).
// ---------------------------------------------------------------------------
__global__ void __launch_bounds__(256) gather_kernel(
    const float* __restrict__ x,
    const float* __restrict__ norm) {
    const int wid = threadIdx.x >> 5;
    const int lane = threadIdx.x & 31;
    const int q = lane >> 3;        // quarter 0..3
    const int ql = lane & 7;        // lane within quarter
    const int nA = blockIdx.x * 16 + 2 * wid;      // exact: 6250*16 = 100000
    const int nB = nA + 1;
    const int myNode = (q < 2) ? nA : nB;

    const int cntA = min(g_cnt[nA], CAP);
    const int cntB = min(g_cnt[nB], CAP);
    const int myCnt = (q < 2) ? cntA : cntB;
    const int cntMax = max(cntA, cntB);

    const int slotCnt = (lane < 16) ? cntA : cntB;
    const int* __restrict__ mySlots =
        g_slots + (size_t)((lane < 16) ? nA : nB) * CAP;
    const int slotClampHi = max(slotCnt - 1, 0);
    const __half* __restrict__ xh = g_xh;

    float4 a0, a1;
    if ((q & 1) == 0) {
        const float4* xs = (const float4*)(x + (size_t)myNode * CHANNELS + ql * 8);
        a0 = xs[0];
        a1 = xs[1];
    } else {
        a0 = make_float4(0.f, 0.f, 0.f, 0.f);
        a1 = make_float4(0.f, 0.f, 0.f, 0.f);
    }

    int sidx_cur = mySlots[min(lane & 15, slotClampHi)];
    for (int e = 0; e < cntMax; e += 16) {
        int sidx_nxt = 0;
        if (e + 16 < cntMax)
            sidx_nxt = mySlots[min(e + 16 + (lane & 15), slotClampHi)];

#pragma unroll
        for (int r = 0; r < 8; r++) {
            int edgeIdx = e + 2 * r + (q & 1);
            int srcLane = ((q >= 2) ? 16 : 0) + 2 * r + (q & 1);
            int s = __shfl_sync(0xffffffffu, sidx_cur, srcLane);
            if (edgeIdx < myCnt) {
                uint4 hv = *(const uint4*)(xh + (size_t)s * CHANNELS + ql * 8);
                float2 f0 = __half22float2(*(const __half2*)&hv.x);
                float2 f1 = __half22float2(*(const __half2*)&hv.y);
                float2 f2 = __half22float2(*(const __half2*)&hv.z);
                float2 f3 = __half22float2(*(const __half2*)&hv.w);
                a0.x += f0.x; a0.y += f0.y; a0.z += f1.x; a0.w += f1.y;
                a1.x += f2.x; a1.y += f2.y; a1.z += f3.x; a1.w += f3.y;
            }
        }
        sidx_cur = sidx_nxt;
    }

    a0.x += __shfl_xor_sync(0xffffffffu, a0.x, 8);
    a0.y += __shfl_xor_sync(0xffffffffu, a0.y, 8);
    a0.z += __shfl_xor_sync(0xffffffffu, a0.z, 8);
    a0.w += __shfl_xor_sync(0xffffffffu, a0.w, 8);
    a1.x += __shfl_xor_sync(0xffffffffu, a1.x, 8);
    a1.y += __shfl_xor_sync(0xffffffffu, a1.y, 8);
    a1.z += __shfl_xor_sync(0xffffffffu, a1.z, 8);
    a1.w += __shfl_xor_sync(0xffffffffu, a1.w, 8);

    if ((q & 1) == 0) {
        float nm = norm[myNode];
        float4* dst = (float4*)(g_agg + (size_t)myNode * CHANNELS + ql * 8);
        dst[0] = make_float4(a0.x * nm, a0.y * nm, a0.z * nm, a0.w * nm);
        dst[1] = make_float4(a1.x * nm, a1.y * nm, a1.z * nm, a1.w * nm);
    }
}

// ---------------------------------------------------------------------------
// Kernel 4: out = g_agg @ W via mma.sync tf32, shared-staged A.
//   Warp: 16 nodes x 64 outputs (8 k-chunks x 8 n-tiles m16n8k8).
//   A: warp's 16 rows are CONTIGUOUS in g_agg -> 8 coalesced LDG.128 into
//      shared (row stride 68 -> fragment LDS (4*gid+tid)%32 conflict-free).
//   B: shared tf32, row stride 72 -> (8*tid+gid)%32 conflict-free.
// ---------------------------------------------------------------------------
#define WSTRIDE 72
#define ASTRIDE 68

__device__ __forceinline__ uint32_t f32_to_tf32(float f) {
    uint32_t r;
    asm("cvt.rna.tf32.f32 %0, %1;" : "=r"(r) : "f"(f));
    return r;
}

__global__ void __launch_bounds__(256) gemm_kernel(
    const float* __restrict__ W,
    float* __restrict__ out) {
    __shared__ uint32_t sW[CHANNELS * WSTRIDE];          // 18 KB
    __shared__ __align__(16) float sA[8][16][ASTRIDE];   // 34 KB

    for (int i = threadIdx.x; i < CHANNELS * CHANNELS; i += blockDim.x) {
        int k = i >> 6;
        int n = i & 63;
        sW[k * WSTRIDE + n] = f32_to_tf32(W[i]);
    }
    __syncthreads();

    const int wid = threadIdx.x >> 5;
    const int lane = threadIdx.x & 31;
    const int gid = lane >> 2;   // group id 0..7
    const int tid = lane & 3;    // thread in group 0..3
    const int base = (blockIdx.x * 8 + wid) * 16;  // first of this warp's 16 nodes

    // --- Stage 16 rows (4 KB contiguous) into shared, coalesced LDG.128 ---
    {
        const float4* src = (const float4*)(g_agg + (size_t)base * CHANNELS);
        // 256 float4 total; lane handles 8 of them.
#pragma unroll
        for (int i = 0; i < 8; i++) {
            int idx = i * 32 + lane;          // 0..255
            int row = idx >> 4;               // /16
            int col4 = idx & 15;
            float4 v;
            if (base + row < N_NODES) v = src[idx];
            else v = make_float4(0.f, 0.f, 0.f, 0.f);
            *(float4*)(&sA[wid][row][col4 * 4]) = v;
        }
    }
    __syncwarp();

    float c[8][4];
#pragma unroll
    for (int nt = 0; nt < 8; nt++)
#pragma unroll
        for (int j = 0; j < 4; j++) c[nt][j] = 0.f;

#pragma unroll
    for (int kc = 0; kc < 8; kc++) {
        const int k0 = kc * 8 + tid;
        // A fragment from shared, conflict-free (stride 68).
        uint32_t a0 = f32_to_tf32(sA[wid][gid][k0]);
        uint32_t a1 = f32_to_tf32(sA[wid][gid + 8][k0]);
        uint32_t a2 = f32_to_tf32(sA[wid][gid][k0 + 4]);
        uint32_t a3 = f32_to_tf32(sA[wid][gid + 8][k0 + 4]);

#pragma unroll
        for (int nt = 0; nt < 8; nt++) {
            uint32_t b0 = sW[(kc * 8 + tid) * WSTRIDE + nt * 8 + gid];
            uint32_t b1 = sW[(kc * 8 + tid + 4) * WSTRIDE + nt * 8 + gid];
            asm volatile(
                "mma.sync.aligned.m16n8k8.row.col.f32.tf32.tf32.f32 "
                "{%0,%1,%2,%3}, {%4,%5,%6,%7}, {%8,%9}, {%0,%1,%2,%3};"
                : "+f"(c[nt][0]), "+f"(c[nt][1]), "+f"(c[nt][2]), "+f"(c[nt][3])
                : "r"(a0), "r"(a1), "r"(a2), "r"(a3), "r"(b0), "r"(b1));
        }
    }

    const int rowLo = base + gid;
    const int rowHi = base + gid + 8;
#pragma unroll
    for (int nt = 0; nt < 8; nt++) {
        if (rowLo < N_NODES)
            *(float2*)(out + (size_t)rowLo * CHANNELS + nt * 8 + 2 * tid) =
                make_float2(c[nt][0], c[nt][1]);
        if (rowHi < N_NODES)
            *(float2*)(out + (size_t)rowHi * CHANNELS + nt * 8 + 2 * tid) =
                make_float2(c[nt][2], c[nt][3]);
    }
}

// ---------------------------------------------------------------------------
extern "C" void kernel_launch(void* const* d_in, const int* in_sizes, int n_in,
                              void* d_out, int out_size) {
    const float* x = (const float*)d_in[0];
    const int* sources = (const int*)d_in[1];
    const int* targets = (const int*)d_in[2];
    const float* norm = (const float*)d_in[3];
    const float* weight = (const float*)d_in[4];
    float* out = (float*)d_out;

    prep_kernel<<<2048, 256>>>(x);
    fill_kernel<<<2048, 256>>>(sources, targets);

    gather_kernel<<<N_NODES / 16, 256>>>(x, norm);   // 6250 blocks
    // 8 warps/block x 16 nodes = 128 nodes/block; 782 blocks covers 100096.
    gemm_kernel<<<(N_NODES + 127) / 128, 256>>>(weight, out);
}

// round 13
// speedup vs baseline: 1.4507x; 1.0948x over previous
#include <cuda_runtime.h>
#include <cuda_fp16.h>
#include <stdint.h>

#define N_NODES 100000
#define CHANNELS 64
#define N_EDGES 4000000
#define CAP 128   // per-node in-edge capacity; P(Poisson(40) >= 128) ~ 3e-27

// Per-node in-edge buckets. g_cnt is zero at module load; the gather kernel
// re-zeroes each counter after consuming it, so every replay starts clean.
__device__ int g_cnt[N_NODES];
__device__ int g_slots[(size_t)N_NODES * CAP];
// fp16 mirror of x
__device__ __align__(16) __half g_xh[(size_t)N_NODES * CHANNELS];
// fp16 aggregated+scaled rows: norm[n] * (x[n] + sum x[src])
__device__ __align__(16) __half g_aggh[(size_t)N_NODES * CHANNELS];

// ---------------------------------------------------------------------------
// Kernel 1: fused  (a) convert x -> fp16 mirror  (b) bucket edges by target.
// The two parts are independent; (a) is HBM-bound, (b) is L2-atomic-bound,
// so fusing overlaps them.
// ---------------------------------------------------------------------------
__global__ void fillconv_kernel(const float* __restrict__ x,
                                const int* __restrict__ srcs,
                                const int* __restrict__ tgts) {
    const int i = blockIdx.x * blockDim.x + threadIdx.x;
    const int stride = gridDim.x * blockDim.x;

    // (a) convert
    const int n4 = N_NODES * CHANNELS / 4;
    const float4* x4 = (const float4*)x;
    uint2* h4 = (uint2*)g_xh;
    for (int k = i; k < n4; k += stride) {
        float4 v = x4[k];
        __half2 a = __floats2half2_rn(v.x, v.y);
        __half2 b = __floats2half2_rn(v.z, v.w);
        uint2 o;
        o.x = *(const unsigned*)&a;
        o.y = *(const unsigned*)&b;
        h4[k] = o;
    }

    // (b) fill buckets
    for (int e = i; e < N_EDGES; e += stride) {
        int t = tgts[e];
        int s = srcs[e];
        int pos = atomicAdd(&g_cnt[t], 1);
        if (pos < CAP) g_slots[(size_t)t * CAP + pos] = s;
    }
}

// ---------------------------------------------------------------------------
// Kernel 2: GATHER (proven loop). Two nodes per warp, quarter-warp per row,
// double-buffered slot chunks. Writes norm-scaled rows as fp16 to g_aggh,
// then zeroes this warp's two counters for the next replay.
// ---------------------------------------------------------------------------
__global__ void __launch_bounds__(256) gather_kernel(
    const float* __restrict__ x,
    const float* __restrict__ norm) {
    const int wid = threadIdx.x >> 5;
    const int lane = threadIdx.x & 31;
    const int q = lane >> 3;        // quarter 0..3
    const int ql = lane & 7;        // lane within quarter
    const int nA = blockIdx.x * 16 + 2 * wid;      // exact: 6250*16 = 100000
    const int nB = nA + 1;
    const int myNode = (q < 2) ? nA : nB;

    const int cntA = min(g_cnt[nA], CAP);
    const int cntB = min(g_cnt[nB], CAP);
    const int myCnt = (q < 2) ? cntA : cntB;
    const int cntMax = max(cntA, cntB);

    const int slotCnt = (lane < 16) ? cntA : cntB;
    const int* __restrict__ mySlots =
        g_slots + (size_t)((lane < 16) ? nA : nB) * CAP;
    const int slotClampHi = max(slotCnt - 1, 0);
    const __half* __restrict__ xh = g_xh;

    float4 a0, a1;
    if ((q & 1) == 0) {
        const float4* xs = (const float4*)(x + (size_t)myNode * CHANNELS + ql * 8);
        a0 = xs[0];
        a1 = xs[1];
    } else {
        a0 = make_float4(0.f, 0.f, 0.f, 0.f);
        a1 = make_float4(0.f, 0.f, 0.f, 0.f);
    }

    int sidx_cur = mySlots[min(lane & 15, slotClampHi)];
    for (int e = 0; e < cntMax; e += 16) {
        int sidx_nxt = 0;
        if (e + 16 < cntMax)
            sidx_nxt = mySlots[min(e + 16 + (lane & 15), slotClampHi)];

#pragma unroll
        for (int r = 0; r < 8; r++) {
            int edgeIdx = e + 2 * r + (q & 1);
            int srcLane = ((q >= 2) ? 16 : 0) + 2 * r + (q & 1);
            int s = __shfl_sync(0xffffffffu, sidx_cur, srcLane);
            if (edgeIdx < myCnt) {
                uint4 hv = *(const uint4*)(xh + (size_t)s * CHANNELS + ql * 8);
                float2 f0 = __half22float2(*(const __half2*)&hv.x);
                float2 f1 = __half22float2(*(const __half2*)&hv.y);
                float2 f2 = __half22float2(*(const __half2*)&hv.z);
                float2 f3 = __half22float2(*(const __half2*)&hv.w);
                a0.x += f0.x; a0.y += f0.y; a0.z += f1.x; a0.w += f1.y;
                a1.x += f2.x; a1.y += f2.y; a1.z += f3.x; a1.w += f3.y;
            }
        }
        sidx_cur = sidx_nxt;
    }

    a0.x += __shfl_xor_sync(0xffffffffu, a0.x, 8);
    a0.y += __shfl_xor_sync(0xffffffffu, a0.y, 8);
    a0.z += __shfl_xor_sync(0xffffffffu, a0.z, 8);
    a0.w += __shfl_xor_sync(0xffffffffu, a0.w, 8);
    a1.x += __shfl_xor_sync(0xffffffffu, a1.x, 8);
    a1.y += __shfl_xor_sync(0xffffffffu, a1.y, 8);
    a1.z += __shfl_xor_sync(0xffffffffu, a1.z, 8);
    a1.w += __shfl_xor_sync(0xffffffffu, a1.w, 8);

    // Even quarters write the norm-scaled row as fp16 (8 ch = 16 B per lane).
    if ((q & 1) == 0) {
        float nm = norm[myNode];
        __half2 h0 = __floats2half2_rn(a0.x * nm, a0.y * nm);
        __half2 h1 = __floats2half2_rn(a0.z * nm, a0.w * nm);
        __half2 h2 = __floats2half2_rn(a1.x * nm, a1.y * nm);
        __half2 h3 = __floats2half2_rn(a1.z * nm, a1.w * nm);
        uint4 o;
        o.x = *(const unsigned*)&h0;
        o.y = *(const unsigned*)&h1;
        o.z = *(const unsigned*)&h2;
        o.w = *(const unsigned*)&h3;
        *(uint4*)(g_aggh + (size_t)myNode * CHANNELS + ql * 8) = o;
    }

    // Reset counters for the next graph replay (statics are zero at load).
    if (lane == 0) {
        g_cnt[nA] = 0;
        g_cnt[nB] = 0;
    }
}

// ---------------------------------------------------------------------------
// Kernel 3: out = agg @ W via mma.sync tf32, shared-staged A (fp16 source).
//   A: warp's 16 rows (2 KB contiguous fp16) -> 4 coalesced LDG.128,
//      expanded to fp32 in shared (stride 68 -> conflict-free fragments).
//   B: shared tf32, stride 72 -> conflict-free.
// ---------------------------------------------------------------------------
#define WSTRIDE 72
#define ASTRIDE 68

__device__ __forceinline__ uint32_t f32_to_tf32(float f) {
    uint32_t r;
    asm("cvt.rna.tf32.f32 %0, %1;" : "=r"(r) : "f"(f));
    return r;
}

__global__ void __launch_bounds__(256) gemm_kernel(
    const float* __restrict__ W,
    float* __restrict__ out) {
    __shared__ uint32_t sW[CHANNELS * WSTRIDE];          // 18 KB
    __shared__ __align__(16) float sA[8][16][ASTRIDE];   // 34 KB

    for (int i = threadIdx.x; i < CHANNELS * CHANNELS; i += blockDim.x) {
        int k = i >> 6;
        int n = i & 63;
        sW[k * WSTRIDE + n] = f32_to_tf32(W[i]);
    }
    __syncthreads();

    const int wid = threadIdx.x >> 5;
    const int lane = threadIdx.x & 31;
    const int gid = lane >> 2;   // group id 0..7
    const int tid = lane & 3;    // thread in group 0..3
    const int base = (blockIdx.x * 8 + wid) * 16;  // first of this warp's 16 nodes

    // --- Stage 16 fp16 rows (2 KB contiguous) into shared as fp32 ---
    {
        const uint4* src = (const uint4*)(g_aggh + (size_t)base * CHANNELS);
        // 128 uint4 total (each = 8 halves); lane handles 4.
#pragma unroll
        for (int i = 0; i < 4; i++) {
            int idx = i * 32 + lane;          // 0..127
            int row = idx >> 3;               // /8
            int col8 = idx & 7;               // which 8-channel group
            uint4 hv;
            if (base + row < N_NODES) hv = src[idx];
            else hv = make_uint4(0u, 0u, 0u, 0u);
            float2 f0 = __half22float2(*(const __half2*)&hv.x);
            float2 f1 = __half22float2(*(const __half2*)&hv.y);
            float2 f2 = __half22float2(*(const __half2*)&hv.z);
            float2 f3 = __half22float2(*(const __half2*)&hv.w);
            float* dst = &sA[wid][row][col8 * 8];
            dst[0] = f0.x; dst[1] = f0.y; dst[2] = f1.x; dst[3] = f1.y;
            dst[4] = f2.x; dst[5] = f2.y; dst[6] = f3.x; dst[7] = f3.y;
        }
    }
    __syncwarp();

    float c[8][4];
#pragma unroll
    for (int nt = 0; nt < 8; nt++)
#pragma unroll
        for (int j = 0; j < 4; j++) c[nt][j] = 0.f;

#pragma unroll
    for (int kc = 0; kc < 8; kc++) {
        const int k0 = kc * 8 + tid;
        uint32_t a0 = f32_to_tf32(sA[wid][gid][k0]);
        uint32_t a1 = f32_to_tf32(sA[wid][gid + 8][k0]);
        uint32_t a2 = f32_to_tf32(sA[wid][gid][k0 + 4]);
        uint32_t a3 = f32_to_tf32(sA[wid][gid + 8][k0 + 4]);

#pragma unroll
        for (int nt = 0; nt < 8; nt++) {
            uint32_t b0 = sW[(kc * 8 + tid) * WSTRIDE + nt * 8 + gid];
            uint32_t b1 = sW[(kc * 8 + tid + 4) * WSTRIDE + nt * 8 + gid];
            asm volatile(
                "mma.sync.aligned.m16n8k8.row.col.f32.tf32.tf32.f32 "
                "{%0,%1,%2,%3}, {%4,%5,%6,%7}, {%8,%9}, {%0,%1,%2,%3};"
                : "+f"(c[nt][0]), "+f"(c[nt][1]), "+f"(c[nt][2]), "+f"(c[nt][3])
                : "r"(a0), "r"(a1), "r"(a2), "r"(a3), "r"(b0), "r"(b1));
        }
    }

    const int rowLo = base + gid;
    const int rowHi = base + gid + 8;
#pragma unroll
    for (int nt = 0; nt < 8; nt++) {
        if (rowLo < N_NODES)
            *(float2*)(out + (size_t)rowLo * CHANNELS + nt * 8 + 2 * tid) =
                make_float2(c[nt][0], c[nt][1]);
        if (rowHi < N_NODES)
            *(float2*)(out + (size_t)rowHi * CHANNELS + nt * 8 + 2 * tid) =
                make_float2(c[nt][2], c[nt][3]);
    }
}

// ---------------------------------------------------------------------------
extern "C" void kernel_launch(void* const* d_in, const int* in_sizes, int n_in,
                              void* d_out, int out_size) {
    const float* x = (const float*)d_in[0];
    const int* sources = (const int*)d_in[1];
    const int* targets = (const int*)d_in[2];
    const float* norm = (const float*)d_in[3];
    const float* weight = (const float*)d_in[4];
    float* out = (float*)d_out;

    fillconv_kernel<<<2048, 256>>>(x, sources, targets);
    gather_kernel<<<N_NODES / 16, 256>>>(x, norm);        // 6250 blocks
    gemm_kernel<<<(N_NODES + 127) / 128, 256>>>(weight, out);  // 782 blocks
}

// round 14
// speedup vs baseline: 1.5212x; 1.0486x over previous
#include <cuda_runtime.h>
#include <cuda_fp16.h>
#include <stdint.h>

#define N_NODES 100000
#define CHANNELS 64
#define N_EDGES 4000000
#define CAP 128   // per-node in-edge capacity; P(Poisson(40) >= 128) ~ 3e-27

// Per-node in-edge buckets. g_cnt is zero at module load; the gather kernel
// re-zeroes each counter after consuming it, so every replay starts clean.
__device__ int g_cnt[N_NODES];
__device__ int g_slots[(size_t)N_NODES * CAP];
// fp16 mirror of x
__device__ __align__(16) __half g_xh[(size_t)N_NODES * CHANNELS];
// fp16 aggregated+scaled rows: norm[n] * (x[n] + sum x[src])
__device__ __align__(16) __half g_aggh[(size_t)N_NODES * CHANNELS];

// ---------------------------------------------------------------------------
// Kernel 1: fused  (a) convert x -> fp16 mirror  (b) bucket edges by target.
// ---------------------------------------------------------------------------
__global__ void fillconv_kernel(const float* __restrict__ x,
                                const int* __restrict__ srcs,
                                const int* __restrict__ tgts) {
    const int i = blockIdx.x * blockDim.x + threadIdx.x;
    const int stride = gridDim.x * blockDim.x;

    // (a) convert
    const int n4 = N_NODES * CHANNELS / 4;
    const float4* x4 = (const float4*)x;
    uint2* h4 = (uint2*)g_xh;
    for (int k = i; k < n4; k += stride) {
        float4 v = x4[k];
        __half2 a = __floats2half2_rn(v.x, v.y);
        __half2 b = __floats2half2_rn(v.z, v.w);
        uint2 o;
        o.x = *(const unsigned*)&a;
        o.y = *(const unsigned*)&b;
        h4[k] = o;
    }

    // (b) fill buckets
    for (int e = i; e < N_EDGES; e += stride) {
        int t = tgts[e];
        int s = srcs[e];
        int pos = atomicAdd(&g_cnt[t], 1);
        if (pos < CAP) g_slots[(size_t)t * CAP + pos] = s;
    }
}

// ---------------------------------------------------------------------------
// Kernel 2: GATHER. Two nodes per warp, quarter-warp per edge row,
// double-buffered slot chunks. Chunk body is explicitly phase-batched
// (SHFL batch -> LDG batch -> accumulate batch) to guarantee MLP=8.
// Self term read from the fp16 mirror. Writes fp16 rows; resets counters.
// ---------------------------------------------------------------------------
__global__ void __launch_bounds__(256) gather_kernel(
    const float* __restrict__ norm) {
    const int wid = threadIdx.x >> 5;
    const int lane = threadIdx.x & 31;
    const int q = lane >> 3;        // quarter 0..3
    const int ql = lane & 7;        // lane within quarter
    const int nA = blockIdx.x * 16 + 2 * wid;      // exact: 6250*16 = 100000
    const int nB = nA + 1;
    const int myNode = (q < 2) ? nA : nB;

    const int cntA = min(g_cnt[nA], CAP);
    const int cntB = min(g_cnt[nB], CAP);
    const int myCnt = (q < 2) ? cntA : cntB;
    const int cntMax = max(cntA, cntB);

    const int slotCnt = (lane < 16) ? cntA : cntB;
    const int* __restrict__ mySlots =
        g_slots + (size_t)((lane < 16) ? nA : nB) * CAP;
    const int slotClampHi = max(slotCnt - 1, 0);
    const __half* __restrict__ xh = g_xh;

    // fp32 accumulators; fold "+ x[n]" (fp16 mirror) into even quarters.
    float4 a0, a1;
    if ((q & 1) == 0) {
        uint4 hv = *(const uint4*)(xh + (size_t)myNode * CHANNELS + ql * 8);
        float2 f0 = __half22float2(*(const __half2*)&hv.x);
        float2 f1 = __half22float2(*(const __half2*)&hv.y);
        float2 f2 = __half22float2(*(const __half2*)&hv.z);
        float2 f3 = __half22float2(*(const __half2*)&hv.w);
        a0 = make_float4(f0.x, f0.y, f1.x, f1.y);
        a1 = make_float4(f2.x, f2.y, f3.x, f3.y);
    } else {
        a0 = make_float4(0.f, 0.f, 0.f, 0.f);
        a1 = make_float4(0.f, 0.f, 0.f, 0.f);
    }

    const int srcLaneBase = ((q >= 2) ? 16 : 0) + (q & 1);

    int sidx_cur = mySlots[min(lane & 15, slotClampHi)];
    for (int e = 0; e < cntMax; e += 16) {
        int sidx_nxt = 0;
        if (e + 16 < cntMax)
            sidx_nxt = mySlots[min(e + 16 + (lane & 15), slotClampHi)];

        // Phase 1: all SHFLs (cheap, independent).
        int s[8];
#pragma unroll
        for (int r = 0; r < 8; r++)
            s[r] = __shfl_sync(0xffffffffu, sidx_cur, srcLaneBase + 2 * r);

        // Phase 2: all 8 predicated loads -> guaranteed 8 in flight.
        uint4 v[8];
#pragma unroll
        for (int r = 0; r < 8; r++) {
            if (e + 2 * r + (q & 1) < myCnt)
                v[r] = *(const uint4*)(xh + (size_t)s[r] * CHANNELS + ql * 8);
            else
                v[r] = make_uint4(0u, 0u, 0u, 0u);
        }

        // Phase 3: convert + accumulate.
#pragma unroll
        for (int r = 0; r < 8; r++) {
            float2 f0 = __half22float2(*(const __half2*)&v[r].x);
            float2 f1 = __half22float2(*(const __half2*)&v[r].y);
            float2 f2 = __half22float2(*(const __half2*)&v[r].z);
            float2 f3 = __half22float2(*(const __half2*)&v[r].w);
            a0.x += f0.x; a0.y += f0.y; a0.z += f1.x; a0.w += f1.y;
            a1.x += f2.x; a1.y += f2.y; a1.z += f3.x; a1.w += f3.y;
        }

        sidx_cur = sidx_nxt;
    }

    a0.x += __shfl_xor_sync(0xffffffffu, a0.x, 8);
    a0.y += __shfl_xor_sync(0xffffffffu, a0.y, 8);
    a0.z += __shfl_xor_sync(0xffffffffu, a0.z, 8);
    a0.w += __shfl_xor_sync(0xffffffffu, a0.w, 8);
    a1.x += __shfl_xor_sync(0xffffffffu, a1.x, 8);
    a1.y += __shfl_xor_sync(0xffffffffu, a1.y, 8);
    a1.z += __shfl_xor_sync(0xffffffffu, a1.z, 8);
    a1.w += __shfl_xor_sync(0xffffffffu, a1.w, 8);

    // Even quarters write the norm-scaled row as fp16 (8 ch = 16 B per lane).
    if ((q & 1) == 0) {
        float nm = norm[myNode];
        __half2 h0 = __floats2half2_rn(a0.x * nm, a0.y * nm);
        __half2 h1 = __floats2half2_rn(a0.z * nm, a0.w * nm);
        __half2 h2 = __floats2half2_rn(a1.x * nm, a1.y * nm);
        __half2 h3 = __floats2half2_rn(a1.z * nm, a1.w * nm);
        uint4 o;
        o.x = *(const unsigned*)&h0;
        o.y = *(const unsigned*)&h1;
        o.z = *(const unsigned*)&h2;
        o.w = *(const unsigned*)&h3;
        *(uint4*)(g_aggh + (size_t)myNode * CHANNELS + ql * 8) = o;
    }

    // Reset counters for the next graph replay (statics are zero at load).
    if (lane == 0) {
        g_cnt[nA] = 0;
        g_cnt[nB] = 0;
    }
}

// ---------------------------------------------------------------------------
// Kernel 3: out = agg @ W via mma.sync tf32, shared-staged A (fp16 source).
// ---------------------------------------------------------------------------
#define WSTRIDE 72
#define ASTRIDE 68

__device__ __forceinline__ uint32_t f32_to_tf32(float f) {
    uint32_t r;
    asm("cvt.rna.tf32.f32 %0, %1;" : "=r"(r) : "f"(f));
    return r;
}

__global__ void __launch_bounds__(256) gemm_kernel(
    const float* __restrict__ W,
    float* __restrict__ out) {
    __shared__ uint32_t sW[CHANNELS * WSTRIDE];          // 18 KB
    __shared__ __align__(16) float sA[8][16][ASTRIDE];   // 34 KB

    for (int i = threadIdx.x; i < CHANNELS * CHANNELS; i += blockDim.x) {
        int k = i >> 6;
        int n = i & 63;
        sW[k * WSTRIDE + n] = f32_to_tf32(W[i]);
    }
    __syncthreads();

    const int wid = threadIdx.x >> 5;
    const int lane = threadIdx.x & 31;
    const int gid = lane >> 2;   // group id 0..7
    const int tid = lane & 3;    // thread in group 0..3
    const int base = (blockIdx.x * 8 + wid) * 16;

    {
        const uint4* src = (const uint4*)(g_aggh + (size_t)base * CHANNELS);
#pragma unroll
        for (int i = 0; i < 4; i++) {
            int idx = i * 32 + lane;          // 0..127
            int row = idx >> 3;
            int col8 = idx & 7;
            uint4 hv;
            if (base + row < N_NODES) hv = src[idx];
            else hv = make_uint4(0u, 0u, 0u, 0u);
            float2 f0 = __half22float2(*(const __half2*)&hv.x);
            float2 f1 = __half22float2(*(const __half2*)&hv.y);
            float2 f2 = __half22float2(*(const __half2*)&hv.z);
            float2 f3 = __half22float2(*(const __half2*)&hv.w);
            float* dst = &sA[wid][row][col8 * 8];
            dst[0] = f0.x; dst[1] = f0.y; dst[2] = f1.x; dst[3] = f1.y;
            dst[4] = f2.x; dst[5] = f2.y; dst[6] = f3.x; dst[7] = f3.y;
        }
    }
    __syncwarp();

    float c[8][4];
#pragma unroll
    for (int nt = 0; nt < 8; nt++)
#pragma unroll
        for (int j = 0; j < 4; j++) c[nt][j] = 0.f;

#pragma unroll
    for (int kc = 0; kc < 8; kc++) {
        const int k0 = kc * 8 + tid;
        uint32_t a0 = f32_to_tf32(sA[wid][gid][k0]);
        uint32_t a1 = f32_to_tf32(sA[wid][gid + 8][k0]);
        uint32_t a2 = f32_to_tf32(sA[wid][gid][k0 + 4]);
        uint32_t a3 = f32_to_tf32(sA[wid][gid + 8][k0 + 4]);

#pragma unroll
        for (int nt = 0; nt < 8; nt++) {
            uint32_t b0 = sW[(kc * 8 + tid) * WSTRIDE + nt * 8 + gid];
            uint32_t b1 = sW[(kc * 8 + tid + 4) * WSTRIDE + nt * 8 + gid];
            asm volatile(
                "mma.sync.aligned.m16n8k8.row.col.f32.tf32.tf32.f32 "
                "{%0,%1,%2,%3}, {%4,%5,%6,%7}, {%8,%9}, {%0,%1,%2,%3};"
                : "+f"(c[nt][0]), "+f"(c[nt][1]), "+f"(c[nt][2]), "+f"(c[nt][3])
                : "r"(a0), "r"(a1), "r"(a2), "r"(a3), "r"(b0), "r"(b1));
        }
    }

    const int rowLo = base + gid;
    const int rowHi = base + gid + 8;
#pragma unroll
    for (int nt = 0; nt < 8; nt++) {
        if (rowLo < N_NODES)
            *(float2*)(out + (size_t)rowLo * CHANNELS + nt * 8 + 2 * tid) =
                make_float2(c[nt][0], c[nt][1]);
        if (rowHi < N_NODES)
            *(float2*)(out + (size_t)rowHi * CHANNELS + nt * 8 + 2 * tid) =
                make_float2(c[nt][2], c[nt][3]);
    }
}

// ---------------------------------------------------------------------------
extern "C" void kernel_launch(void* const* d_in, const int* in_sizes, int n_in,
                              void* d_out, int out_size) {
    const float* x = (const float*)d_in[0];
    const int* sources = (const int*)d_in[1];
    const int* targets = (const int*)d_in[2];
    const float* norm = (const float*)d_in[3];
    const float* weight = (const float*)d_in[4];
    float* out = (float*)d_out;

    fillconv_kernel<<<2048, 256>>>(x, sources, targets);
    gather_kernel<<<N_NODES / 16, 256>>>(norm);                // 6250 blocks
    gemm_kernel<<<(N_NODES + 127) / 128, 256>>>(weight, out);  // 782 blocks
}

// round 15
// speedup vs baseline: 1.5486x; 1.0181x over previous
#include <cuda_runtime.h>
#include <cuda_fp16.h>
#include <stdint.h>

#define N_NODES 100000
#define CHANNELS 64
#define N_EDGES 4000000
#define CAP 128   // per-node in-edge capacity; P(Poisson(40) >= 128) ~ 3e-27

// Per-node in-edge buckets. g_cnt is zero at module load; the gather kernel
// re-zeroes each counter after consuming it, so every replay starts clean.
__device__ int g_cnt[N_NODES];
__device__ int g_slots[(size_t)N_NODES * CAP];
// fp16 mirror of x
__device__ __align__(16) __half g_xh[(size_t)N_NODES * CHANNELS];
// fp16 aggregated+scaled rows: norm[n] * (x[n] + sum x[src])
__device__ __align__(16) __half g_aggh[(size_t)N_NODES * CHANNELS];

// ---------------------------------------------------------------------------
// Kernel 1: fused  (a) convert x -> fp16 mirror  (b) bucket edges by target.
// ---------------------------------------------------------------------------
__global__ void fillconv_kernel(const float* __restrict__ x,
                                const int* __restrict__ srcs,
                                const int* __restrict__ tgts) {
    const int i = blockIdx.x * blockDim.x + threadIdx.x;
    const int stride = gridDim.x * blockDim.x;

    // (a) convert
    const int n4 = N_NODES * CHANNELS / 4;
    const float4* x4 = (const float4*)x;
    uint2* h4 = (uint2*)g_xh;
    for (int k = i; k < n4; k += stride) {
        float4 v = x4[k];
        __half2 a = __floats2half2_rn(v.x, v.y);
        __half2 b = __floats2half2_rn(v.z, v.w);
        uint2 o;
        o.x = *(const unsigned*)&a;
        o.y = *(const unsigned*)&b;
        h4[k] = o;
    }

    // (b) fill buckets
    for (int e = i; e < N_EDGES; e += stride) {
        int t = tgts[e];
        int s = srcs[e];
        int pos = atomicAdd(&g_cnt[t], 1);
        if (pos < CAP) g_slots[(size_t)t * CAP + pos] = s;
    }
}

// ---------------------------------------------------------------------------
// Kernel 2: GATHER (proven; unchanged from R14). Two nodes per warp,
// quarter-warp per edge row, double-buffered slot chunks, phase-batched MLP=8.
// ---------------------------------------------------------------------------
__global__ void __launch_bounds__(256) gather_kernel(
    const float* __restrict__ norm) {
    const int wid = threadIdx.x >> 5;
    const int lane = threadIdx.x & 31;
    const int q = lane >> 3;        // quarter 0..3
    const int ql = lane & 7;        // lane within quarter
    const int nA = blockIdx.x * 16 + 2 * wid;      // exact: 6250*16 = 100000
    const int nB = nA + 1;
    const int myNode = (q < 2) ? nA : nB;

    const int cntA = min(g_cnt[nA], CAP);
    const int cntB = min(g_cnt[nB], CAP);
    const int myCnt = (q < 2) ? cntA : cntB;
    const int cntMax = max(cntA, cntB);

    const int slotCnt = (lane < 16) ? cntA : cntB;
    const int* __restrict__ mySlots =
        g_slots + (size_t)((lane < 16) ? nA : nB) * CAP;
    const int slotClampHi = max(slotCnt - 1, 0);
    const __half* __restrict__ xh = g_xh;

    float4 a0, a1;
    if ((q & 1) == 0) {
        uint4 hv = *(const uint4*)(xh + (size_t)myNode * CHANNELS + ql * 8);
        float2 f0 = __half22float2(*(const __half2*)&hv.x);
        float2 f1 = __half22float2(*(const __half2*)&hv.y);
        float2 f2 = __half22float2(*(const __half2*)&hv.z);
        float2 f3 = __half22float2(*(const __half2*)&hv.w);
        a0 = make_float4(f0.x, f0.y, f1.x, f1.y);
        a1 = make_float4(f2.x, f2.y, f3.x, f3.y);
    } else {
        a0 = make_float4(0.f, 0.f, 0.f, 0.f);
        a1 = make_float4(0.f, 0.f, 0.f, 0.f);
    }

    const int srcLaneBase = ((q >= 2) ? 16 : 0) + (q & 1);

    int sidx_cur = mySlots[min(lane & 15, slotClampHi)];
    for (int e = 0; e < cntMax; e += 16) {
        int sidx_nxt = 0;
        if (e + 16 < cntMax)
            sidx_nxt = mySlots[min(e + 16 + (lane & 15), slotClampHi)];

        int s[8];
#pragma unroll
        for (int r = 0; r < 8; r++)
            s[r] = __shfl_sync(0xffffffffu, sidx_cur, srcLaneBase + 2 * r);

        uint4 v[8];
#pragma unroll
        for (int r = 0; r < 8; r++) {
            if (e + 2 * r + (q & 1) < myCnt)
                v[r] = *(const uint4*)(xh + (size_t)s[r] * CHANNELS + ql * 8);
            else
                v[r] = make_uint4(0u, 0u, 0u, 0u);
        }

#pragma unroll
        for (int r = 0; r < 8; r++) {
            float2 f0 = __half22float2(*(const __half2*)&v[r].x);
            float2 f1 = __half22float2(*(const __half2*)&v[r].y);
            float2 f2 = __half22float2(*(const __half2*)&v[r].z);
            float2 f3 = __half22float2(*(const __half2*)&v[r].w);
            a0.x += f0.x; a0.y += f0.y; a0.z += f1.x; a0.w += f1.y;
            a1.x += f2.x; a1.y += f2.y; a1.z += f3.x; a1.w += f3.y;
        }

        sidx_cur = sidx_nxt;
    }

    a0.x += __shfl_xor_sync(0xffffffffu, a0.x, 8);
    a0.y += __shfl_xor_sync(0xffffffffu, a0.y, 8);
    a0.z += __shfl_xor_sync(0xffffffffu, a0.z, 8);
    a0.w += __shfl_xor_sync(0xffffffffu, a0.w, 8);
    a1.x += __shfl_xor_sync(0xffffffffu, a1.x, 8);
    a1.y += __shfl_xor_sync(0xffffffffu, a1.y, 8);
    a1.z += __shfl_xor_sync(0xffffffffu, a1.z, 8);
    a1.w += __shfl_xor_sync(0xffffffffu, a1.w, 8);

    if ((q & 1) == 0) {
        float nm = norm[myNode];
        __half2 h0 = __floats2half2_rn(a0.x * nm, a0.y * nm);
        __half2 h1 = __floats2half2_rn(a0.z * nm, a0.w * nm);
        __half2 h2 = __floats2half2_rn(a1.x * nm, a1.y * nm);
        __half2 h3 = __floats2half2_rn(a1.z * nm, a1.w * nm);
        uint4 o;
        o.x = *(const unsigned*)&h0;
        o.y = *(const unsigned*)&h1;
        o.z = *(const unsigned*)&h2;
        o.w = *(const unsigned*)&h3;
        *(uint4*)(g_aggh + (size_t)myNode * CHANNELS + ql * 8) = o;
    }

    if (lane == 0) {
        g_cnt[nA] = 0;
        g_cnt[nB] = 0;
    }
}

// ---------------------------------------------------------------------------
// Kernel 3: out = agg @ W via fp16 HMMA (m16n8k16), ldmatrix-fed.
//   A: warp's 16 fp16 rows (2 KB contiguous) -> raw uint4 copies into shared
//      (stride 72 halves = 144 B -> banks 4r mod 32, ldmatrix conflict-free),
//      fragments via ldmatrix.x4 (4 per warp).
//   B: W as fp16 in shared, same stride; fragments via ldmatrix.x2.trans.
//   32 HMMA (k16) per warp; fp32 accumulators; fp32 output.
// ---------------------------------------------------------------------------
#define HSTRIDE 72  // halves; 144 B per row

__device__ __forceinline__ uint32_t smem_u32(const void* p) {
    return (uint32_t)__cvta_generic_to_shared(p);
}

__global__ void __launch_bounds__(256) gemm_kernel(
    const float* __restrict__ W,
    float* __restrict__ out) {
    __shared__ __align__(16) __half sWh[CHANNELS * HSTRIDE];       // 9 KB
    __shared__ __align__(16) __half sA[8][16 * HSTRIDE];           // 18 KB

    for (int i = threadIdx.x; i < CHANNELS * CHANNELS; i += blockDim.x) {
        int k = i >> 6;
        int n = i & 63;
        sWh[k * HSTRIDE + n] = __float2half_rn(W[i]);
    }
    __syncthreads();

    const int wid = threadIdx.x >> 5;
    const int lane = threadIdx.x & 31;
    const int gid = lane >> 2;   // group id 0..7
    const int tid = lane & 3;    // thread in group 0..3
    const int base = (blockIdx.x * 8 + wid) * 16;  // warp's first node

    // --- Stage 16 fp16 rows (raw copy, strided) ---
    {
        const uint4* src = (const uint4*)(g_aggh + (size_t)base * CHANNELS);
#pragma unroll
        for (int i = 0; i < 4; i++) {
            int idx = i * 32 + lane;          // 0..127 (row = idx/8, col8 = idx%8)
            int row = idx >> 3;
            int col8 = idx & 7;
            uint4 hv;
            if (base + row < N_NODES) hv = src[idx];
            else hv = make_uint4(0u, 0u, 0u, 0u);
            *(uint4*)(&sA[wid][row * HSTRIDE + col8 * 8]) = hv;
        }
    }
    __syncwarp();

    float c[8][4];
#pragma unroll
    for (int nt = 0; nt < 8; nt++)
#pragma unroll
        for (int j = 0; j < 4; j++) c[nt][j] = 0.f;

    // A-fragment lane->address mapping (ldmatrix x4):
    //   lanes 0-15  -> row (lane&15), k-offset kc*16
    //   lanes 16-31 -> row (lane&15), k-offset kc*16+8
    const int arow = lane & 15;
    const int akoff = (lane >> 4) * 8;
    // B-fragment mapping (x2.trans): lanes 0-15 -> W row kc*16+(lane&15).
    const int brow = lane & 15;

#pragma unroll
    for (int kc = 0; kc < 4; kc++) {
        uint32_t a0, a1, a2, a3;
        {
            uint32_t addr = smem_u32(&sA[wid][arow * HSTRIDE + kc * 16 + akoff]);
            asm volatile(
                "ldmatrix.sync.aligned.m8n8.x4.shared.b16 {%0,%1,%2,%3}, [%4];"
                : "=r"(a0), "=r"(a1), "=r"(a2), "=r"(a3) : "r"(addr));
        }
#pragma unroll
        for (int nt = 0; nt < 8; nt++) {
            uint32_t b0, b1;
            uint32_t addr = smem_u32(&sWh[(kc * 16 + brow) * HSTRIDE + nt * 8]);
            asm volatile(
                "ldmatrix.sync.aligned.m8n8.x2.trans.shared.b16 {%0,%1}, [%2];"
                : "=r"(b0), "=r"(b1) : "r"(addr));
            asm volatile(
                "mma.sync.aligned.m16n8k16.row.col.f32.f16.f16.f32 "
                "{%0,%1,%2,%3}, {%4,%5,%6,%7}, {%8,%9}, {%0,%1,%2,%3};"
                : "+f"(c[nt][0]), "+f"(c[nt][1]), "+f"(c[nt][2]), "+f"(c[nt][3])
                : "r"(a0), "r"(a1), "r"(a2), "r"(a3), "r"(b0), "r"(b1));
        }
    }

    const int rowLo = base + gid;
    const int rowHi = base + gid + 8;
#pragma unroll
    for (int nt = 0; nt < 8; nt++) {
        if (rowLo < N_NODES)
            *(float2*)(out + (size_t)rowLo * CHANNELS + nt * 8 + 2 * tid) =
                make_float2(c[nt][0], c[nt][1]);
        if (rowHi < N_NODES)
            *(float2*)(out + (size_t)rowHi * CHANNELS + nt * 8 + 2 * tid) =
                make_float2(c[nt][2], c[nt][3]);
    }
}

// ---------------------------------------------------------------------------
extern "C" void kernel_launch(void* const* d_in, const int* in_sizes, int n_in,
                              void* d_out, int out_size) {
    const float* x = (const float*)d_in[0];
    const int* sources = (const int*)d_in[1];
    const int* targets = (const int*)d_in[2];
    const float* norm = (const float*)d_in[3];
    const float* weight = (const float*)d_in[4];
    float* out = (float*)d_out;

    fillconv_kernel<<<2048, 256>>>(x, sources, targets);
    gather_kernel<<<N_NODES / 16, 256>>>(norm);                // 6250 blocks
    gemm_kernel<<<(N_NODES + 127) / 128, 256>>>(weight, out);  // 782 blocks
}

// round 16
// speedup vs baseline: 1.5762x; 1.0178x over previous
#include <cuda_runtime.h>
#include <cuda_fp16.h>
#include <stdint.h>

#define N_NODES 100000
#define CHANNELS 64
#define N_EDGES 4000000
#define CAP 128   // per-node in-edge capacity; P(Poisson(40) >= 128) ~ 3e-27

// Per-node in-edge buckets. g_cnt is zero at module load; the gather kernel
// re-zeroes each counter after consuming it, so every replay starts clean.
__device__ int g_cnt[N_NODES];
__device__ int g_slots[(size_t)N_NODES * CAP];
// fp16 mirror of x
__device__ __align__(16) __half g_xh[(size_t)N_NODES * CHANNELS];
// fp16 aggregated+scaled rows: norm[n] * (x[n] + sum x[src])
__device__ __align__(16) __half g_aggh[(size_t)N_NODES * CHANNELS];

// ---------------------------------------------------------------------------
// Kernel 1: fused  (a) convert x -> fp16 mirror  (b) bucket edges by target.
// (b) now processes 4 edges per iteration from int4 loads; the four
// atomic->store chains are independent -> 4x memory-level parallelism.
// ---------------------------------------------------------------------------
__global__ void fillconv_kernel(const float* __restrict__ x,
                                const int* __restrict__ srcs,
                                const int* __restrict__ tgts) {
    const int i = blockIdx.x * blockDim.x + threadIdx.x;
    const int stride = gridDim.x * blockDim.x;

    // (a) convert
    const int n4 = N_NODES * CHANNELS / 4;
    const float4* x4 = (const float4*)x;
    uint2* h4 = (uint2*)g_xh;
    for (int k = i; k < n4; k += stride) {
        float4 v = x4[k];
        __half2 a = __floats2half2_rn(v.x, v.y);
        __half2 b = __floats2half2_rn(v.z, v.w);
        uint2 o;
        o.x = *(const unsigned*)&a;
        o.y = *(const unsigned*)&b;
        h4[k] = o;
    }

    // (b) fill buckets, 4 edges per iteration (independent chains)
    const int e4 = N_EDGES / 4;
    const int4* s4 = (const int4*)srcs;
    const int4* t4 = (const int4*)tgts;
    for (int k = i; k < e4; k += stride) {
        int4 s = s4[k];
        int4 t = t4[k];
        int p0 = atomicAdd(&g_cnt[t.x], 1);
        int p1 = atomicAdd(&g_cnt[t.y], 1);
        int p2 = atomicAdd(&g_cnt[t.z], 1);
        int p3 = atomicAdd(&g_cnt[t.w], 1);
        if (p0 < CAP) g_slots[(size_t)t.x * CAP + p0] = s.x;
        if (p1 < CAP) g_slots[(size_t)t.y * CAP + p1] = s.y;
        if (p2 < CAP) g_slots[(size_t)t.z * CAP + p2] = s.z;
        if (p3 < CAP) g_slots[(size_t)t.w * CAP + p3] = s.w;
    }
}

// ---------------------------------------------------------------------------
// Kernel 2: GATHER. Two nodes per warp, quarter-warp per edge row,
// double-buffered slot chunks, phase-batched MLP=8. Row loads use __ldcg
// (L2-only) -- random over 12.8 MB, L1 hit rate ~2%, allocation is waste.
// ---------------------------------------------------------------------------
__global__ void __launch_bounds__(256) gather_kernel(
    const float* __restrict__ norm) {
    const int wid = threadIdx.x >> 5;
    const int lane = threadIdx.x & 31;
    const int q = lane >> 3;        // quarter 0..3
    const int ql = lane & 7;        // lane within quarter
    const int nA = blockIdx.x * 16 + 2 * wid;      // exact: 6250*16 = 100000
    const int nB = nA + 1;
    const int myNode = (q < 2) ? nA : nB;

    const int cntA = min(g_cnt[nA], CAP);
    const int cntB = min(g_cnt[nB], CAP);
    const int myCnt = (q < 2) ? cntA : cntB;
    const int cntMax = max(cntA, cntB);

    const int slotCnt = (lane < 16) ? cntA : cntB;
    const int* __restrict__ mySlots =
        g_slots + (size_t)((lane < 16) ? nA : nB) * CAP;
    const int slotClampHi = max(slotCnt - 1, 0);
    const __half* __restrict__ xh = g_xh;

    float4 a0, a1;
    if ((q & 1) == 0) {
        uint4 hv = __ldcg((const uint4*)(xh + (size_t)myNode * CHANNELS + ql * 8));
        float2 f0 = __half22float2(*(const __half2*)&hv.x);
        float2 f1 = __half22float2(*(const __half2*)&hv.y);
        float2 f2 = __half22float2(*(const __half2*)&hv.z);
        float2 f3 = __half22float2(*(const __half2*)&hv.w);
        a0 = make_float4(f0.x, f0.y, f1.x, f1.y);
        a1 = make_float4(f2.x, f2.y, f3.x, f3.y);
    } else {
        a0 = make_float4(0.f, 0.f, 0.f, 0.f);
        a1 = make_float4(0.f, 0.f, 0.f, 0.f);
    }

    const int srcLaneBase = ((q >= 2) ? 16 : 0) + (q & 1);

    int sidx_cur = mySlots[min(lane & 15, slotClampHi)];
    for (int e = 0; e < cntMax; e += 16) {
        int sidx_nxt = 0;
        if (e + 16 < cntMax)
            sidx_nxt = mySlots[min(e + 16 + (lane & 15), slotClampHi)];

        int s[8];
#pragma unroll
        for (int r = 0; r < 8; r++)
            s[r] = __shfl_sync(0xffffffffu, sidx_cur, srcLaneBase + 2 * r);

        uint4 v[8];
#pragma unroll
        for (int r = 0; r < 8; r++) {
            if (e + 2 * r + (q & 1) < myCnt)
                v[r] = __ldcg((const uint4*)(xh + (size_t)s[r] * CHANNELS + ql * 8));
            else
                v[r] = make_uint4(0u, 0u, 0u, 0u);
        }

#pragma unroll
        for (int r = 0; r < 8; r++) {
            float2 f0 = __half22float2(*(const __half2*)&v[r].x);
            float2 f1 = __half22float2(*(const __half2*)&v[r].y);
            float2 f2 = __half22float2(*(const __half2*)&v[r].z);
            float2 f3 = __half22float2(*(const __half2*)&v[r].w);
            a0.x += f0.x; a0.y += f0.y; a0.z += f1.x; a0.w += f1.y;
            a1.x += f2.x; a1.y += f2.y; a1.z += f3.x; a1.w += f3.y;
        }

        sidx_cur = sidx_nxt;
    }

    a0.x += __shfl_xor_sync(0xffffffffu, a0.x, 8);
    a0.y += __shfl_xor_sync(0xffffffffu, a0.y, 8);
    a0.z += __shfl_xor_sync(0xffffffffu, a0.z, 8);
    a0.w += __shfl_xor_sync(0xffffffffu, a0.w, 8);
    a1.x += __shfl_xor_sync(0xffffffffu, a1.x, 8);
    a1.y += __shfl_xor_sync(0xffffffffu, a1.y, 8);
    a1.z += __shfl_xor_sync(0xffffffffu, a1.z, 8);
    a1.w += __shfl_xor_sync(0xffffffffu, a1.w, 8);

    if ((q & 1) == 0) {
        float nm = norm[myNode];
        __half2 h0 = __floats2half2_rn(a0.x * nm, a0.y * nm);
        __half2 h1 = __floats2half2_rn(a0.z * nm, a0.w * nm);
        __half2 h2 = __floats2half2_rn(a1.x * nm, a1.y * nm);
        __half2 h3 = __floats2half2_rn(a1.z * nm, a1.w * nm);
        uint4 o;
        o.x = *(const unsigned*)&h0;
        o.y = *(const unsigned*)&h1;
        o.z = *(const unsigned*)&h2;
        o.w = *(const unsigned*)&h3;
        *(uint4*)(g_aggh + (size_t)myNode * CHANNELS + ql * 8) = o;
    }

    if (lane == 0) {
        g_cnt[nA] = 0;
        g_cnt[nB] = 0;
    }
}

// ---------------------------------------------------------------------------
// Kernel 3: out = agg @ W via fp16 HMMA (m16n8k16), ldmatrix-fed. (proven)
// ---------------------------------------------------------------------------
#define HSTRIDE 72  // halves; 144 B per row

__device__ __forceinline__ uint32_t smem_u32(const void* p) {
    return (uint32_t)__cvta_generic_to_shared(p);
}

__global__ void __launch_bounds__(256) gemm_kernel(
    const float* __restrict__ W,
    float* __restrict__ out) {
    __shared__ __align__(16) __half sWh[CHANNELS * HSTRIDE];       // 9 KB
    __shared__ __align__(16) __half sA[8][16 * HSTRIDE];           // 18 KB

    for (int i = threadIdx.x; i < CHANNELS * CHANNELS; i += blockDim.x) {
        int k = i >> 6;
        int n = i & 63;
        sWh[k * HSTRIDE + n] = __float2half_rn(W[i]);
    }
    __syncthreads();

    const int wid = threadIdx.x >> 5;
    const int lane = threadIdx.x & 31;
    const int gid = lane >> 2;   // group id 0..7
    const int tid = lane & 3;    // thread in group 0..3
    const int base = (blockIdx.x * 8 + wid) * 16;  // warp's first node

    {
        const uint4* src = (const uint4*)(g_aggh + (size_t)base * CHANNELS);
#pragma unroll
        for (int i = 0; i < 4; i++) {
            int idx = i * 32 + lane;          // 0..127
            int row = idx >> 3;
            int col8 = idx & 7;
            uint4 hv;
            if (base + row < N_NODES) hv = src[idx];
            else hv = make_uint4(0u, 0u, 0u, 0u);
            *(uint4*)(&sA[wid][row * HSTRIDE + col8 * 8]) = hv;
        }
    }
    __syncwarp();

    float c[8][4];
#pragma unroll
    for (int nt = 0; nt < 8; nt++)
#pragma unroll
        for (int j = 0; j < 4; j++) c[nt][j] = 0.f;

    const int arow = lane & 15;
    const int akoff = (lane >> 4) * 8;
    const int brow = lane & 15;

#pragma unroll
    for (int kc = 0; kc < 4; kc++) {
        uint32_t a0, a1, a2, a3;
        {
            uint32_t addr = smem_u32(&sA[wid][arow * HSTRIDE + kc * 16 + akoff]);
            asm volatile(
                "ldmatrix.sync.aligned.m8n8.x4.shared.b16 {%0,%1,%2,%3}, [%4];"
                : "=r"(a0), "=r"(a1), "=r"(a2), "=r"(a3) : "r"(addr));
        }
#pragma unroll
        for (int nt = 0; nt < 8; nt++) {
            uint32_t b0, b1;
            uint32_t addr = smem_u32(&sWh[(kc * 16 + brow) * HSTRIDE + nt * 8]);
            asm volatile(
                "ldmatrix.sync.aligned.m8n8.x2.trans.shared.b16 {%0,%1}, [%2];"
                : "=r"(b0), "=r"(b1) : "r"(addr));
            asm volatile(
                "mma.sync.aligned.m16n8k16.row.col.f32.f16.f16.f32 "
                "{%0,%1,%2,%3}, {%4,%5,%6,%7}, {%8,%9}, {%0,%1,%2,%3};"
                : "+f"(c[nt][0]), "+f"(c[nt][1]), "+f"(c[nt][2]), "+f"(c[nt][3])
                : "r"(a0), "r"(a1), "r"(a2), "r"(a3), "r"(b0), "r"(b1));
        }
    }

    const int rowLo = base + gid;
    const int rowHi = base + gid + 8;
#pragma unroll
    for (int nt = 0; nt < 8; nt++) {
        if (rowLo < N_NODES)
            *(float2*)(out + (size_t)rowLo * CHANNELS + nt * 8 + 2 * tid) =
                make_float2(c[nt][0], c[nt][1]);
        if (rowHi < N_NODES)
            *(float2*)(out + (size_t)rowHi * CHANNELS + nt * 8 + 2 * tid) =
                make_float2(c[nt][2], c[nt][3]);
    }
}

// ---------------------------------------------------------------------------
extern "C" void kernel_launch(void* const* d_in, const int* in_sizes, int n_in,
                              void* d_out, int out_size) {
    const float* x = (const float*)d_in[0];
    const int* sources = (const int*)d_in[1];
    const int* targets = (const int*)d_in[2];
    const float* norm = (const float*)d_in[3];
    const float* weight = (const float*)d_in[4];
    float* out = (float*)d_out;

    fillconv_kernel<<<2048, 256>>>(x, sources, targets);
    gather_kernel<<<N_NODES / 16, 256>>>(norm);                // 6250 blocks
    gemm_kernel<<<(N_NODES + 127) / 128, 256>>>(weight, out);  // 782 blocks
}